// round 2
// baseline (speedup 1.0000x reference)
#include <cuda_runtime.h>

// Problem constants (from reference)
#define NN   50000
#define FEAT 64
#define F4   16          // FEAT / 4 (float4 chunks per node row)
#define LL   4
#define NNZ  800000

#define NODE_THREADS (NN * F4)        // 800000
#define EDGE_THREADS (NNZ * F4)       // 12800000

// Persistent state (module-scope device memory; fully re-initialized every call)
__device__ float4 g_Uk [NN * F4];
__device__ float4 g_WU [LL][NN * F4];
__device__ float4 g_Lam[LL][NN * F4];
__device__ float4 g_tmp[LL][NN * F4];
__device__ float4 g_agg[NN * F4];

__constant__ float c_nu[LL] = {0.0f, 1.0f, 0.25f, 0.0625f};

// Vector atomic add: native float4 overload on sm_90+ (CUDA >= 12.1).
__device__ __forceinline__ void red_add_v4(float4* addr, float4 v) {
#if __CUDA_ARCH__ >= 900
    atomicAdd(addr, v);
#else
    atomicAdd(&addr->x, v.x);
    atomicAdd(&addr->y, v.y);
    atomicAdd(&addr->z, v.z);
    atomicAdd(&addr->w, v.w);
#endif
}

// ---------------------------------------------------------------------------
// Iter 0 init: Uk = d/(d+mu2_0) * x ; zero WU and Lam (full state reset)
// ---------------------------------------------------------------------------
__global__ __launch_bounds__(256) void k_init(const float4* __restrict__ x,
                                              const float*  __restrict__ d) {
    int i = blockIdx.x * blockDim.x + threadIdx.x;
    if (i >= NODE_THREADS) return;
    int n = i >> 4;
    float dn = __ldg(&d[n]);
    float s = dn / (dn + 1.0f);            // mu2_0 = 1
    float4 xv = __ldg(&x[i]);
    g_Uk[i] = make_float4(s * xv.x, s * xv.y, s * xv.z, s * xv.w);
    float4 z = make_float4(0.f, 0.f, 0.f, 0.f);
#pragma unroll
    for (int l = 0; l < LL; l++) {
        g_WU[l][i]  = z;
        g_Lam[l][i] = z;
    }
}

// ---------------------------------------------------------------------------
// WU_l += W_l @ Uk  (fused over all 4 operators; 16 threads per edge)
// ---------------------------------------------------------------------------
__global__ __launch_bounds__(256) void k_wu(const float* __restrict__ w,
                                            const int*   __restrict__ rows,
                                            const int*   __restrict__ cols) {
    int gid = blockIdx.x * blockDim.x + threadIdx.x;
    if (gid >= EDGE_THREADS) return;
    int e = gid >> 4;
    int c = gid & 15;
    int col = __ldg(&cols[e]);
    int row = __ldg(&rows[e]);
    float4 u = g_Uk[col * F4 + c];
#pragma unroll
    for (int l = 0; l < LL; l++) {
        float wl = __ldg(&w[l * NNZ + e]);
        red_add_v4(&g_WU[l][row * F4 + c],
                   make_float4(wl * u.x, wl * u.y, wl * u.z, wl * u.w));
    }
}

// ---------------------------------------------------------------------------
// Q update + dual update + tmp precompute for next iteration.
// tmp_l = mu2_next * Q_l + Lam_new_l.  Also zeroes WU and agg for next iter.
// ---------------------------------------------------------------------------
__global__ __launch_bounds__(256) void k_q(const float* __restrict__ d,
                                           float mu2, float inv_mu2, float mu2n) {
    int i = blockIdx.x * blockDim.x + threadIdx.x;
    if (i >= NODE_THREADS) return;
    int n = i >> 4;
    float dn = __ldg(&d[n]);
    float4 z = make_float4(0.f, 0.f, 0.f, 0.f);
#pragma unroll
    for (int l = 0; l < LL; l++) {
        float4 wu  = g_WU[l][i];
        float4 lam = g_Lam[l][i];
        float eta = c_nu[l] * inv_mu2 * dn;
        float4 q, lam2, tv;
        {
            float xm;
            xm = wu.x - lam.x * inv_mu2;
            q.x = fmaxf(xm - eta, 0.f) - fmaxf(-xm - eta, 0.f);
            xm = wu.y - lam.y * inv_mu2;
            q.y = fmaxf(xm - eta, 0.f) - fmaxf(-xm - eta, 0.f);
            xm = wu.z - lam.z * inv_mu2;
            q.z = fmaxf(xm - eta, 0.f) - fmaxf(-xm - eta, 0.f);
            xm = wu.w - lam.w * inv_mu2;
            q.w = fmaxf(xm - eta, 0.f) - fmaxf(-xm - eta, 0.f);
        }
        lam2.x = lam.x + mu2 * (q.x - wu.x);
        lam2.y = lam.y + mu2 * (q.y - wu.y);
        lam2.z = lam.z + mu2 * (q.z - wu.z);
        lam2.w = lam.w + mu2 * (q.w - wu.w);
        tv.x = mu2n * q.x + lam2.x;
        tv.y = mu2n * q.y + lam2.y;
        tv.z = mu2n * q.z + lam2.z;
        tv.w = mu2n * q.w + lam2.w;
        g_Lam[l][i] = lam2;
        g_tmp[l][i] = tv;
        g_WU[l][i]  = z;
    }
    g_agg[i] = z;
}

// ---------------------------------------------------------------------------
// agg += Sum_l W_l @ tmp_l  (fused: 4 gathers, 1 scatter per edge-chunk)
// ---------------------------------------------------------------------------
__global__ __launch_bounds__(256) void k_agg(const float* __restrict__ w,
                                             const int*   __restrict__ rows,
                                             const int*   __restrict__ cols) {
    int gid = blockIdx.x * blockDim.x + threadIdx.x;
    if (gid >= EDGE_THREADS) return;
    int e = gid >> 4;
    int c = gid & 15;
    int col = __ldg(&cols[e]);
    int row = __ldg(&rows[e]);
    float4 acc = make_float4(0.f, 0.f, 0.f, 0.f);
#pragma unroll
    for (int l = 0; l < LL; l++) {
        float wl = __ldg(&w[l * NNZ + e]);
        float4 t = g_tmp[l][col * F4 + c];
        acc.x += wl * t.x;
        acc.y += wl * t.y;
        acc.z += wl * t.z;
        acc.w += wl * t.w;
    }
    red_add_v4(&g_agg[row * F4 + c], acc);
}

// ---------------------------------------------------------------------------
// U update: Uk = (d*x + agg) / (d + mu2).  Writes g_Uk, or d_out on final.
// ---------------------------------------------------------------------------
__global__ __launch_bounds__(256) void k_u(const float4* __restrict__ x,
                                           const float*  __restrict__ d,
                                           float mu2, float4* outp) {
    int i = blockIdx.x * blockDim.x + threadIdx.x;
    if (i >= NODE_THREADS) return;
    int n = i >> 4;
    float dn = __ldg(&d[n]);
    float s = 1.0f / (dn + mu2);
    float4 a  = g_agg[i];
    float4 xv = __ldg(&x[i]);
    float4 r = make_float4(s * (dn * xv.x + a.x),
                           s * (dn * xv.y + a.y),
                           s * (dn * xv.z + a.z),
                           s * (dn * xv.w + a.w));
    if (outp) outp[i] = r;
    else      g_Uk[i] = r;
}

// ---------------------------------------------------------------------------
// Launch sequence: 5 ADMM iterations, last iteration only needs the U update.
// ---------------------------------------------------------------------------
extern "C" void kernel_launch(void* const* d_in, const int* in_sizes, int n_in,
                              void* d_out, int out_size) {
    const float4* x    = (const float4*)d_in[0];  // [N, 64] f32
    const float*  w    = (const float*) d_in[1];  // [L, NNZ]
    const float*  d    = (const float*) d_in[2];  // [N]
    const int*    rows = (const int*)   d_in[3];  // [NNZ]
    const int*    cols = (const int*)   d_in[4];  // [NNZ]

    const float mu2s[6] = {1.0f, 1.1f, 1.21f, 1.331f, 1.4641f, 1.61051f};

    const int NB_NODE = (NODE_THREADS + 255) / 256;   // 3125
    const int NB_EDGE = (EDGE_THREADS + 255) / 256;   // 50000

    // ---- iteration 0 (tmp = 0 -> agg = 0; Uk closed form) ----
    k_init<<<NB_NODE, 256>>>(x, d);
    k_wu<<<NB_EDGE, 256>>>(w, rows, cols);
    k_q<<<NB_NODE, 256>>>(d, mu2s[0], 1.0f / mu2s[0], mu2s[1]);

    // ---- iterations 1..4 ----
    for (int it = 1; it < 5; it++) {
        bool fin = (it == 4);
        k_agg<<<NB_EDGE, 256>>>(w, rows, cols);
        k_u<<<NB_NODE, 256>>>(x, d, mu2s[it], fin ? (float4*)d_out : (float4*)nullptr);
        if (!fin) {
            k_wu<<<NB_EDGE, 256>>>(w, rows, cols);
            k_q<<<NB_NODE, 256>>>(d, mu2s[it], 1.0f / mu2s[it], mu2s[it + 1]);
        }
    }
}

// round 3
// speedup vs baseline: 1.8496x; 1.8496x over previous
#include <cuda_runtime.h>

#define NN   50000
#define FEAT 64
#define F4   16
#define LL   4
#define NNZ  800000

#define NODE_THREADS (NN * F4)   // 800000

// ---------------- persistent scratch (rebuilt every call) ----------------
__device__ float4 g_Uk [NN * F4];
__device__ float4 g_Lam[LL][NN * F4];
__device__ float4 g_tmp[LL][NN * F4];

__device__ int    g_cnt  [NN];
__device__ int    g_start[NN];
__device__ int    g_fill [NN];
__device__ int    g_total;
__device__ int    g_csr_col[NNZ];
__device__ float4 g_csr_w  [NNZ];   // 4 operator weights per edge, packed

__constant__ float c_nu[LL] = {0.0f, 1.0f, 0.25f, 0.0625f};

// ---------------------------------------------------------------------------
// Setup: row histogram -> segment alloc (unordered, no scan) -> edge scatter
// ---------------------------------------------------------------------------
__global__ __launch_bounds__(256) void k_zero() {
    int i = blockIdx.x * blockDim.x + threadIdx.x;
    if (i < NN) g_cnt[i] = 0;
    if (i == 0) g_total = 0;
}

__global__ __launch_bounds__(256) void k_hist(const int* __restrict__ rows) {
    int e = blockIdx.x * blockDim.x + threadIdx.x;
    if (e < NNZ) atomicAdd(&g_cnt[__ldg(&rows[e])], 1);
}

__global__ __launch_bounds__(256) void k_alloc() {
    int i = blockIdx.x * blockDim.x + threadIdx.x;
    if (i >= NN) return;
    int c = g_cnt[i];
    int s = atomicAdd(&g_total, c);
    g_start[i] = s;
    g_fill[i]  = s;
}

__global__ __launch_bounds__(256) void k_scatter(const int*   __restrict__ rows,
                                                 const int*   __restrict__ cols,
                                                 const float* __restrict__ w) {
    int e = blockIdx.x * blockDim.x + threadIdx.x;
    if (e >= NNZ) return;
    int r = __ldg(&rows[e]);
    int p = atomicAdd(&g_fill[r], 1);
    g_csr_col[p] = __ldg(&cols[e]);
    g_csr_w[p] = make_float4(__ldg(&w[e]),
                             __ldg(&w[NNZ + e]),
                             __ldg(&w[2 * NNZ + e]),
                             __ldg(&w[3 * NNZ + e]));
}

// ---------------------------------------------------------------------------
// Iter 0: Uk = d/(d+1) * x ; Lam = 0
// ---------------------------------------------------------------------------
__global__ __launch_bounds__(256) void k_init(const float4* __restrict__ x,
                                              const float*  __restrict__ d) {
    int i = blockIdx.x * blockDim.x + threadIdx.x;
    if (i >= NODE_THREADS) return;
    int n = i >> 4;
    float dn = __ldg(&d[n]);
    float s = dn / (dn + 1.0f);
    float4 xv = __ldg(&x[i]);
    g_Uk[i] = make_float4(s * xv.x, s * xv.y, s * xv.z, s * xv.w);
    float4 z = make_float4(0.f, 0.f, 0.f, 0.f);
#pragma unroll
    for (int l = 0; l < LL; l++) g_Lam[l][i] = z;
}

// ---------------------------------------------------------------------------
// WU_l = W_l @ Uk (row-gather, registers) fused with Q/dual/tmp updates.
// tmp_l = mu2n*Q_l + Lam'_l for the NEXT iteration's U update.
// ---------------------------------------------------------------------------
__global__ __launch_bounds__(256) void k_wu_q(const float* __restrict__ d,
                                              float mu2, float inv_mu2, float mu2n) {
    int i = blockIdx.x * blockDim.x + threadIdx.x;
    if (i >= NODE_THREADS) return;
    int row = i >> 4;
    int c   = i & 15;
    int ks  = g_start[row];
    int ke  = ks + g_cnt[row];

    float4 wu[LL];
#pragma unroll
    for (int l = 0; l < LL; l++) wu[l] = make_float4(0.f, 0.f, 0.f, 0.f);

    for (int k = ks; k < ke; k++) {
        int    col = g_csr_col[k];
        float4 wv  = g_csr_w[k];
        float4 u   = g_Uk[col * F4 + c];
        wu[0].x += wv.x * u.x; wu[0].y += wv.x * u.y; wu[0].z += wv.x * u.z; wu[0].w += wv.x * u.w;
        wu[1].x += wv.y * u.x; wu[1].y += wv.y * u.y; wu[1].z += wv.y * u.z; wu[1].w += wv.y * u.w;
        wu[2].x += wv.z * u.x; wu[2].y += wv.z * u.y; wu[2].z += wv.z * u.z; wu[2].w += wv.z * u.w;
        wu[3].x += wv.w * u.x; wu[3].y += wv.w * u.y; wu[3].z += wv.w * u.z; wu[3].w += wv.w * u.w;
    }

    float dn = __ldg(&d[row]);
#pragma unroll
    for (int l = 0; l < LL; l++) {
        float4 lam = g_Lam[l][i];
        float eta = c_nu[l] * inv_mu2 * dn;
        float4 q, lam2, tv;
        float xm;
        xm = wu[l].x - lam.x * inv_mu2;
        q.x = fmaxf(xm - eta, 0.f) - fmaxf(-xm - eta, 0.f);
        xm = wu[l].y - lam.y * inv_mu2;
        q.y = fmaxf(xm - eta, 0.f) - fmaxf(-xm - eta, 0.f);
        xm = wu[l].z - lam.z * inv_mu2;
        q.z = fmaxf(xm - eta, 0.f) - fmaxf(-xm - eta, 0.f);
        xm = wu[l].w - lam.w * inv_mu2;
        q.w = fmaxf(xm - eta, 0.f) - fmaxf(-xm - eta, 0.f);
        lam2.x = lam.x + mu2 * (q.x - wu[l].x);
        lam2.y = lam.y + mu2 * (q.y - wu[l].y);
        lam2.z = lam.z + mu2 * (q.z - wu[l].z);
        lam2.w = lam.w + mu2 * (q.w - wu[l].w);
        tv.x = mu2n * q.x + lam2.x;
        tv.y = mu2n * q.y + lam2.y;
        tv.z = mu2n * q.z + lam2.z;
        tv.w = mu2n * q.w + lam2.w;
        g_Lam[l][i] = lam2;
        g_tmp[l][i] = tv;
    }
}

// ---------------------------------------------------------------------------
// agg = Sum_l W_l @ tmp_l (row-gather, registers) fused with U update.
// Writes g_Uk, or d_out on the final iteration.
// ---------------------------------------------------------------------------
__global__ __launch_bounds__(256) void k_agg_u(const float4* __restrict__ x,
                                               const float*  __restrict__ d,
                                               float mu2, float4* outp) {
    int i = blockIdx.x * blockDim.x + threadIdx.x;
    if (i >= NODE_THREADS) return;
    int row = i >> 4;
    int c   = i & 15;
    int ks  = g_start[row];
    int ke  = ks + g_cnt[row];

    float4 acc = make_float4(0.f, 0.f, 0.f, 0.f);
    for (int k = ks; k < ke; k++) {
        int    col = g_csr_col[k];
        float4 wv  = g_csr_w[k];
        int    o   = col * F4 + c;
        float4 t0 = g_tmp[0][o];
        float4 t1 = g_tmp[1][o];
        float4 t2 = g_tmp[2][o];
        float4 t3 = g_tmp[3][o];
        acc.x += wv.x * t0.x + wv.y * t1.x + wv.z * t2.x + wv.w * t3.x;
        acc.y += wv.x * t0.y + wv.y * t1.y + wv.z * t2.y + wv.w * t3.y;
        acc.z += wv.x * t0.z + wv.y * t1.z + wv.z * t2.z + wv.w * t3.z;
        acc.w += wv.x * t0.w + wv.y * t1.w + wv.z * t2.w + wv.w * t3.w;
    }

    float dn = __ldg(&d[row]);
    float s = 1.0f / (dn + mu2);
    float4 xv = __ldg(&x[i]);
    float4 r = make_float4(s * (dn * xv.x + acc.x),
                           s * (dn * xv.y + acc.y),
                           s * (dn * xv.z + acc.z),
                           s * (dn * xv.w + acc.w));
    if (outp) outp[i] = r;
    else      g_Uk[i] = r;
}

// ---------------------------------------------------------------------------
extern "C" void kernel_launch(void* const* d_in, const int* in_sizes, int n_in,
                              void* d_out, int out_size) {
    const float4* x    = (const float4*)d_in[0];
    const float*  w    = (const float*) d_in[1];
    const float*  d    = (const float*) d_in[2];
    const int*    rows = (const int*)   d_in[3];
    const int*    cols = (const int*)   d_in[4];

    const float mu2s[6] = {1.0f, 1.1f, 1.21f, 1.331f, 1.4641f, 1.61051f};

    const int NB_NODE  = (NODE_THREADS + 255) / 256;  // 3125
    const int NB_N     = (NN + 255) / 256;            // 196
    const int NB_E     = (NNZ + 255) / 256;           // 3125

    // ---- per-call CSR build (graph-capturable, deterministic work) ----
    k_zero   <<<NB_N, 256>>>();
    k_hist   <<<NB_E, 256>>>(rows);
    k_alloc  <<<NB_N, 256>>>();
    k_scatter<<<NB_E, 256>>>(rows, cols, w);

    // ---- iteration 0 (Q=Lam=0 -> closed-form U) ----
    k_init<<<NB_NODE, 256>>>(x, d);
    k_wu_q<<<NB_NODE, 256>>>(d, mu2s[0], 1.0f / mu2s[0], mu2s[1]);

    // ---- iterations 1..4 (last one: U update only, to d_out) ----
    for (int it = 1; it < 5; it++) {
        bool fin = (it == 4);
        k_agg_u<<<NB_NODE, 256>>>(x, d, mu2s[it], fin ? (float4*)d_out : (float4*)nullptr);
        if (!fin)
            k_wu_q<<<NB_NODE, 256>>>(d, mu2s[it], 1.0f / mu2s[it], mu2s[it + 1]);
    }
}

// round 4
// speedup vs baseline: 1.9575x; 1.0583x over previous
#include <cuda_runtime.h>

#define NN   50000
#define FEAT 64
#define F4   16
#define LL   4
#define NNZ  800000

#define NODE_THREADS (NN * F4)   // 800000

// ---------------- persistent scratch (rebuilt every call) ----------------
__device__ float4 g_Uk [NN * F4];
__device__ float4 g_Lam[LL][NN * F4];
__device__ float4 g_tmp[LL][NN * F4];
__device__ float4 g_agg[NN * F4];

// CSR (row-grouped, for WU gather) and CSC (col-grouped, for agg scatter)
__device__ int    g_rcnt [NN];
__device__ int    g_rstart[NN];
__device__ int    g_rfill [NN];
__device__ int    g_ccnt [NN];
__device__ int    g_cstart[NN];
__device__ int    g_cfill [NN];
__device__ int    g_total_r;
__device__ int    g_total_c;
__device__ int    g_csr_col[NNZ];
__device__ float4 g_csr_w  [NNZ];
__device__ int    g_csc_row[NNZ];
__device__ float4 g_csc_w  [NNZ];

__constant__ float c_nu[LL] = {0.0f, 1.0f, 0.25f, 0.0625f};

__device__ __forceinline__ void red_add_v4(float4* addr, float4 v) {
    atomicAdd(addr, v);   // RED.E.ADD.F32.V4 on sm_90+
}

// ---------------------------------------------------------------------------
// Setup
// ---------------------------------------------------------------------------
__global__ __launch_bounds__(256) void k_zero() {
    int i = blockIdx.x * blockDim.x + threadIdx.x;
    if (i < NN) { g_rcnt[i] = 0; g_ccnt[i] = 0; }
    if (i == 0) { g_total_r = 0; g_total_c = 0; }
}

__global__ __launch_bounds__(256) void k_hist(const int* __restrict__ rows,
                                              const int* __restrict__ cols) {
    int e = blockIdx.x * blockDim.x + threadIdx.x;
    if (e < NNZ) {
        atomicAdd(&g_rcnt[__ldg(&rows[e])], 1);
        atomicAdd(&g_ccnt[__ldg(&cols[e])], 1);
    }
}

// Warp-aggregated segment allocation (2 global atomics per warp, order-free).
__global__ __launch_bounds__(256) void k_alloc() {
    int i = blockIdx.x * blockDim.x + threadIdx.x;
    int lane = threadIdx.x & 31;
    int cr = (i < NN) ? g_rcnt[i] : 0;
    int cc = (i < NN) ? g_ccnt[i] : 0;
    int sr = cr, sc = cc;
#pragma unroll
    for (int o = 1; o < 32; o <<= 1) {
        int tr = __shfl_up_sync(0xffffffffu, sr, o);
        int tc = __shfl_up_sync(0xffffffffu, sc, o);
        if (lane >= o) { sr += tr; sc += tc; }
    }
    int baser = 0, basec = 0;
    if (lane == 31) {
        baser = atomicAdd(&g_total_r, sr);
        basec = atomicAdd(&g_total_c, sc);
    }
    baser = __shfl_sync(0xffffffffu, baser, 31);
    basec = __shfl_sync(0xffffffffu, basec, 31);
    if (i < NN) {
        int rs = baser + sr - cr;
        int cs = basec + sc - cc;
        g_rstart[i] = rs;  g_rfill[i] = rs;
        g_cstart[i] = cs;  g_cfill[i] = cs;
    }
}

__global__ __launch_bounds__(256) void k_scatter(const int*   __restrict__ rows,
                                                 const int*   __restrict__ cols,
                                                 const float* __restrict__ w) {
    int e = blockIdx.x * blockDim.x + threadIdx.x;
    if (e >= NNZ) return;
    int r = __ldg(&rows[e]);
    int c = __ldg(&cols[e]);
    float4 w4 = make_float4(__ldg(&w[e]),
                            __ldg(&w[NNZ + e]),
                            __ldg(&w[2 * NNZ + e]),
                            __ldg(&w[3 * NNZ + e]));
    int p = atomicAdd(&g_rfill[r], 1);
    g_csr_col[p] = c;
    g_csr_w[p]   = w4;
    int q = atomicAdd(&g_cfill[c], 1);
    g_csc_row[q] = r;
    g_csc_w[q]   = w4;
}

// ---------------------------------------------------------------------------
// Iter 0: Uk = d/(d+1) * x ; Lam = 0 ; agg = 0
// ---------------------------------------------------------------------------
__global__ __launch_bounds__(256) void k_init(const float4* __restrict__ x,
                                              const float*  __restrict__ d) {
    int i = blockIdx.x * blockDim.x + threadIdx.x;
    if (i >= NODE_THREADS) return;
    int n = i >> 4;
    float dn = __ldg(&d[n]);
    float s = dn / (dn + 1.0f);
    float4 xv = __ldg(&x[i]);
    g_Uk[i] = make_float4(s * xv.x, s * xv.y, s * xv.z, s * xv.w);
    float4 z = make_float4(0.f, 0.f, 0.f, 0.f);
#pragma unroll
    for (int l = 0; l < LL; l++) g_Lam[l][i] = z;
    g_agg[i] = z;
}

// ---------------------------------------------------------------------------
// WU_l = W_l @ Uk (CSR row-gather into registers) fused with Q/dual/tmp.
// ---------------------------------------------------------------------------
__global__ __launch_bounds__(256) void k_wu_q(const float* __restrict__ d,
                                              float mu2, float inv_mu2, float mu2n) {
    int i = blockIdx.x * blockDim.x + threadIdx.x;
    if (i >= NODE_THREADS) return;
    int row = i >> 4;
    int c   = i & 15;
    int ks  = g_rstart[row];
    int ke  = ks + g_rcnt[row];

    float4 wu[LL];
#pragma unroll
    for (int l = 0; l < LL; l++) wu[l] = make_float4(0.f, 0.f, 0.f, 0.f);

    for (int k = ks; k < ke; k++) {
        int    col = g_csr_col[k];
        float4 wv  = g_csr_w[k];
        float4 u   = g_Uk[col * F4 + c];
        wu[0].x += wv.x * u.x; wu[0].y += wv.x * u.y; wu[0].z += wv.x * u.z; wu[0].w += wv.x * u.w;
        wu[1].x += wv.y * u.x; wu[1].y += wv.y * u.y; wu[1].z += wv.y * u.z; wu[1].w += wv.y * u.w;
        wu[2].x += wv.z * u.x; wu[2].y += wv.z * u.y; wu[2].z += wv.z * u.z; wu[2].w += wv.z * u.w;
        wu[3].x += wv.w * u.x; wu[3].y += wv.w * u.y; wu[3].z += wv.w * u.z; wu[3].w += wv.w * u.w;
    }

    float dn = __ldg(&d[row]);
#pragma unroll
    for (int l = 0; l < LL; l++) {
        float4 lam = g_Lam[l][i];
        float eta = c_nu[l] * inv_mu2 * dn;
        float4 q, lam2, tv;
        float xm;
        xm = wu[l].x - lam.x * inv_mu2;
        q.x = fmaxf(xm - eta, 0.f) - fmaxf(-xm - eta, 0.f);
        xm = wu[l].y - lam.y * inv_mu2;
        q.y = fmaxf(xm - eta, 0.f) - fmaxf(-xm - eta, 0.f);
        xm = wu[l].z - lam.z * inv_mu2;
        q.z = fmaxf(xm - eta, 0.f) - fmaxf(-xm - eta, 0.f);
        xm = wu[l].w - lam.w * inv_mu2;
        q.w = fmaxf(xm - eta, 0.f) - fmaxf(-xm - eta, 0.f);
        lam2.x = lam.x + mu2 * (q.x - wu[l].x);
        lam2.y = lam.y + mu2 * (q.y - wu[l].y);
        lam2.z = lam.z + mu2 * (q.z - wu[l].z);
        lam2.w = lam.w + mu2 * (q.w - wu[l].w);
        tv.x = mu2n * q.x + lam2.x;
        tv.y = mu2n * q.y + lam2.y;
        tv.z = mu2n * q.z + lam2.z;
        tv.w = mu2n * q.w + lam2.w;
        g_Lam[l][i] = lam2;
        g_tmp[l][i] = tv;
    }
}

// ---------------------------------------------------------------------------
// agg += Sum_l W_l @ tmp_l  -- CSC scatter: tmp row loaded ONCE per col,
// one RED.v4 per edge per feature-chunk.
// ---------------------------------------------------------------------------
__global__ __launch_bounds__(256) void k_agg_sc() {
    int i = blockIdx.x * blockDim.x + threadIdx.x;
    if (i >= NODE_THREADS) return;
    int col = i >> 4;
    int c   = i & 15;
    int ks  = g_cstart[col];
    int ke  = ks + g_ccnt[col];
    if (ks == ke) return;

    int o = col * F4 + c;
    float4 t0 = g_tmp[0][o];
    float4 t1 = g_tmp[1][o];
    float4 t2 = g_tmp[2][o];
    float4 t3 = g_tmp[3][o];

    for (int k = ks; k < ke; k++) {
        int    row = g_csc_row[k];
        float4 wv  = g_csc_w[k];
        float4 v;
        v.x = wv.x * t0.x + wv.y * t1.x + wv.z * t2.x + wv.w * t3.x;
        v.y = wv.x * t0.y + wv.y * t1.y + wv.z * t2.y + wv.w * t3.y;
        v.z = wv.x * t0.z + wv.y * t1.z + wv.z * t2.z + wv.w * t3.z;
        v.w = wv.x * t0.w + wv.y * t1.w + wv.z * t2.w + wv.w * t3.w;
        red_add_v4(&g_agg[row * F4 + c], v);
    }
}

// ---------------------------------------------------------------------------
// U update: Uk = (d*x + agg)/(d + mu2); re-zeroes agg for the next scatter.
// ---------------------------------------------------------------------------
__global__ __launch_bounds__(256) void k_u(const float4* __restrict__ x,
                                           const float*  __restrict__ d,
                                           float mu2, float4* outp) {
    int i = blockIdx.x * blockDim.x + threadIdx.x;
    if (i >= NODE_THREADS) return;
    int n = i >> 4;
    float dn = __ldg(&d[n]);
    float s = 1.0f / (dn + mu2);
    float4 a  = g_agg[i];
    float4 xv = __ldg(&x[i]);
    float4 r = make_float4(s * (dn * xv.x + a.x),
                           s * (dn * xv.y + a.y),
                           s * (dn * xv.z + a.z),
                           s * (dn * xv.w + a.w));
    if (outp) outp[i] = r;
    else      g_Uk[i] = r;
    g_agg[i] = make_float4(0.f, 0.f, 0.f, 0.f);
}

// ---------------------------------------------------------------------------
extern "C" void kernel_launch(void* const* d_in, const int* in_sizes, int n_in,
                              void* d_out, int out_size) {
    const float4* x    = (const float4*)d_in[0];
    const float*  w    = (const float*) d_in[1];
    const float*  d    = (const float*) d_in[2];
    const int*    rows = (const int*)   d_in[3];
    const int*    cols = (const int*)   d_in[4];

    const float mu2s[6] = {1.0f, 1.1f, 1.21f, 1.331f, 1.4641f, 1.61051f};

    const int NB_NODE = (NODE_THREADS + 255) / 256;  // 3125
    const int NB_N    = (NN + 255) / 256;            // 196
    const int NB_E    = (NNZ + 255) / 256;           // 3125

    // ---- per-call CSR+CSC build ----
    k_zero   <<<NB_N, 256>>>();
    k_hist   <<<NB_E, 256>>>(rows, cols);
    k_alloc  <<<NB_N, 256>>>();
    k_scatter<<<NB_E, 256>>>(rows, cols, w);

    // ---- iteration 0 (Q=Lam=0 -> closed-form U) ----
    k_init<<<NB_NODE, 256>>>(x, d);
    k_wu_q<<<NB_NODE, 256>>>(d, mu2s[0], 1.0f / mu2s[0], mu2s[1]);

    // ---- iterations 1..4 (last: U update only, to d_out) ----
    for (int it = 1; it < 5; it++) {
        bool fin = (it == 4);
        k_agg_sc<<<NB_NODE, 256>>>();
        k_u<<<NB_NODE, 256>>>(x, d, mu2s[it], fin ? (float4*)d_out : (float4*)nullptr);
        if (!fin)
            k_wu_q<<<NB_NODE, 256>>>(d, mu2s[it], 1.0f / mu2s[it], mu2s[it + 1]);
    }
}